// round 17
// baseline (speedup 1.0000x reference)
#include <cuda_runtime.h>

// DegreePrediction: y[u] = sum_{s,t,v} (x*W_t)[s,t] * (W_r*r_zeros + r_const)[s,t,u,v]
// N = 80. Three 80^4 fp32 tensors (491.5 MB) streamed once.
//
// R17: tail-split with depth-3 bodies. R16 (depth-3, 6.88 TB/s) saturated the
// per-warp-depth lever; remaining ~9.4us of DRAM-idle matches the staggered
// drain of the last of 3.6 block-generations (~20us K4 blocks). R13's taper
// failed because its K1/K2 bodies were depth-1 (slower mid-kernel); here ALL
// bodies use the depth-3 immediate-offset pipeline:
//   bids [0,1400):    K=4, slices 0..5599   (R16 body)
//   bids [1400,2200): K=1, slices 5600..6399 (~6us drain blocks)
//
// Layout: slice = 1600 contiguous float4 = 5*320; iter it (k=it/5, j=it%5)
// reads float4 tid + 320*j + 1600*k -> u = tid/20 + 16*j.

#define NN 80
#define SLICE_F4 1600
#define SLICE_FLOATS (NN * NN)      // 6400
#define THREADS 320
#define J_ITERS 5
#define DEPTH 3
#define B4 1400
#define B1 800
#define GRID_TOTAL (B4 + B1)        // 2200

__device__ float    g_scratch[NN];   // zero at load; kernel restores to zero
__device__ unsigned g_count;         // ditto

__device__ __forceinline__ unsigned atom_inc_acq_rel(unsigned* p) {
    unsigned old;
    asm volatile("atom.add.acq_rel.gpu.global.u32 %0, [%1], 1;"
                 : "=r"(old) : "l"(p) : "memory");
    return old;
}

template <int K>
__device__ __forceinline__ void stream_slices(
    const float* __restrict__ x, const float* __restrict__ wt,
    const float* __restrict__ r_zeros, const float* __restrict__ r_const,
    const float* __restrict__ weights_r,
    int s0, int tid, float acc[J_ITERS])
{
    const int NITER = K * J_ITERS;
    const size_t base = (size_t)s0 * SLICE_FLOATS;
    const float4* __restrict__ rz = reinterpret_cast<const float4*>(r_zeros   + base);
    const float4* __restrict__ rc = reinterpret_cast<const float4*>(r_const   + base);
    const float4* __restrict__ wr = reinterpret_cast<const float4*>(weights_r + base);

    // depth-3 rotating prefetch buffers; all offsets compile-time immediates
    float4 zb[DEPTH], cb[DEPTH], wb[DEPTH];
#pragma unroll
    for (int s = 0; s < DEPTH; s++) {
        const int itn = (s < NITER) ? s : (NITER - 1);
        const int p = tid + THREADS * (itn % J_ITERS) + SLICE_F4 * (itn / J_ITERS);
        zb[s] = __ldcs(&rz[p]);
        cb[s] = __ldcs(&rc[p]);
        wb[s] = __ldcs(&wr[p]);
    }

#pragma unroll
    for (int it = 0; it < NITER; it++) {
        const int cur = it % DEPTH;
        const int k = it / J_ITERS;
        const int j = it % J_ITERS;

        const float a = __ldg(&x[s0 + k]) * __ldg(&wt[s0 + k]);

        const float4 z = zb[cur];
        const float4 c = cb[cur];
        const float4 w = wb[cur];

        if (it + DEPTH < NITER) {
            const int itn = it + DEPTH;
            const int pn = tid + THREADS * (itn % J_ITERS) + SLICE_F4 * (itn / J_ITERS);
            zb[cur] = __ldcs(&rz[pn]);
            cb[cur] = __ldcs(&rc[pn]);
            wb[cur] = __ldcs(&wr[pn]);
        }

        float t = (c.x + c.y) + (c.z + c.w);
        t = fmaf(w.x, z.x, t);
        t = fmaf(w.y, z.y, t);
        t = fmaf(w.z, z.z, t);
        t = fmaf(w.w, z.w, t);
        acc[j] = fmaf(a, t, acc[j]);
    }
}

__global__ __launch_bounds__(THREADS, 3)
void degree_pred_kernel(const float* __restrict__ x,
                        const float* __restrict__ r_zeros,
                        const float* __restrict__ r_const,
                        const float* __restrict__ weights_t,
                        const float* __restrict__ weights_r,
                        float* __restrict__ out)
{
    __shared__ float y_part[J_ITERS][THREADS];
    __shared__ bool is_last;
    const int tid = threadIdx.x;
    const int bid = blockIdx.x;

    float acc[J_ITERS];
#pragma unroll
    for (int j = 0; j < J_ITERS; j++) acc[j] = 0.0f;

    if (bid < B4) {
        stream_slices<4>(x, weights_t, r_zeros, r_const, weights_r,
                         bid * 4, tid, acc);
    } else {
        stream_slices<1>(x, weights_t, r_zeros, r_const, weights_r,
                         4 * B4 + (bid - B4), tid, acc);
    }

    // ---- epilogue (once per block): STS transpose + 80-thread gather ----
#pragma unroll
    for (int j = 0; j < J_ITERS; j++)
        y_part[j][tid] = acc[j];
    __syncthreads();

    if (tid < NN) {
        const int u = tid;
        const int j = u >> 4;            // u / 16
        const int b = (u & 15) * 20;     // first of 20 contributing threads
        float s = 0.0f;
#pragma unroll
        for (int d = 0; d < 20; d++)
            s += y_part[j][b + d];
        atomicAdd(&g_scratch[u], s);     // relaxed; published by acq_rel below
    }
    __syncthreads();

    // ---- last-block finalize ----
    if (tid == 0)
        is_last = (atom_inc_acq_rel(&g_count) == (unsigned)(GRID_TOTAL - 1));
    __syncthreads();

    if (is_last) {
        if (tid < NN) {
            float v = __ldcg(&g_scratch[tid]);   // L2 read, coherent w/ atomics
            out[tid] = v;
            g_scratch[tid] = 0.0f;               // restore initial state
        }
        __syncthreads();
        if (tid == 0) g_count = 0u;              // restore initial state
    }
}

extern "C" void kernel_launch(void* const* d_in, const int* in_sizes, int n_in,
                              void* d_out, int out_size)
{
    const float* x         = (const float*)d_in[0];
    const float* r_zeros   = (const float*)d_in[1];
    const float* r_const   = (const float*)d_in[2];
    const float* weights_t = (const float*)d_in[3];
    const float* weights_r = (const float*)d_in[4];
    float* out = (float*)d_out;

    degree_pred_kernel<<<GRID_TOTAL, THREADS>>>(x, r_zeros, r_const,
                                                weights_t, weights_r, out);
}